// round 5
// baseline (speedup 1.0000x reference)
#include <cuda_runtime.h>
#include <cooperative_groups.h>
#include <cstdint>
namespace cg = cooperative_groups;

#define ROWS   4096
#define FDIM   16384
#define HALF   8192           // floats per cluster-CTA (32 KB)
#define BINS   128
#define NFEAT  257            // 128 counts + 129 boundaries
#define FPAD   260
#define OUT    64
#define HB     512
#define NW     (HB / 32)      // 16 warps
#define GROWS  16             // rows per GEMM CTA

// Inter-kernel scratch (no allocs allowed)
__device__ __align__(16) float g_cnt[ROWS * 2 * BINS];  // per-rank partial counts
__device__ __align__(16) float g_mnw[ROWS * 2];         // (min, width) per row
__device__ __align__(16) float g_WT[FPAD * OUT];        // transposed+padded W

__device__ __forceinline__ uint32_t smem_u32(const void* p) {
    uint32_t a;
    asm("{ .reg .u64 t; cvta.to.shared.u64 t, %1; cvt.u32.u64 %0, t; }" : "=r"(a) : "l"(p));
    return a;
}

// ---------------------------------------------------------------------------
// Kernel 1: cluster of 2 CTAs per row; each CTA TMA-loads a 32 KB half,
// computes local min/max, exchanges via one DSMEM read, bins its half,
// writes partial counts to global. 4 CTAs/SM -> 100% occupancy.
// ---------------------------------------------------------------------------
__global__ __launch_bounds__(HB, 4) __cluster_dims__(2, 1, 1)
void hist_kernel(const float* __restrict__ x, const float* __restrict__ W) {
    extern __shared__ __align__(16) float sdata[];      // 8192 floats = 32 KB

    __shared__ unsigned int hist[NW * BINS];            // 8 KB
    __shared__ float s_red[2 * NW];
    __shared__ float s_mnmx[2];                         // local (mn, mx) -> peer reads
    __shared__ float s_fin[2];                          // global (mn, width)
    __shared__ __align__(8) unsigned long long mbar;

    cg::cluster_group cluster = cg::this_cluster();

    const unsigned bid  = blockIdx.x;
    const int      row  = bid >> 1;
    const unsigned rank = bid & 1;
    const int tid  = threadIdx.x;
    const int warp = tid >> 5;
    const int lane = tid & 31;

    // zero per-warp histograms
    #pragma unroll
    for (int k = 0; k < (NW * BINS) / HB; k++)
        hist[tid + k * HB] = 0u;

    const uint32_t mbar_a = smem_u32(&mbar);
    const uint32_t data_a = smem_u32(sdata);

    if (tid == 0) {
        asm volatile("mbarrier.init.shared.b64 [%0], 1;" :: "r"(mbar_a) : "memory");
        asm volatile("fence.proxy.async.shared::cta;" ::: "memory");
    }
    __syncthreads();

    if (tid == 0) {
        asm volatile("mbarrier.arrive.expect_tx.shared.b64 _, [%0], %1;"
                     :: "r"(mbar_a), "r"(HALF * 4) : "memory");
        const float* src = x + (size_t)row * FDIM + rank * HALF;
        asm volatile("cp.async.bulk.shared::cta.global.mbarrier::complete_tx::bytes "
                     "[%0], [%1], %2, [%3];"
                     :: "r"(data_a), "l"(src), "r"(HALF * 4), "r"(mbar_a) : "memory");
    }

    // overlap the one-time W transpose with the TMA (first 64 blocks, 1 out col each)
    if (bid < OUT && tid < FPAD) {
        g_WT[tid * OUT + bid] = (tid < NFEAT) ? W[bid * NFEAT + tid] : 0.0f;
    }

    // wait for TMA (parity 0)
    {
        uint32_t done;
        asm volatile("{\n\t.reg .pred p;\n\t"
                     "mbarrier.try_wait.parity.acquire.cta.shared::cta.b64 p, [%1], 0;\n\t"
                     "selp.b32 %0, 1, 0, p;\n\t}"
                     : "=r"(done) : "r"(mbar_a) : "memory");
        while (!done) {
            asm volatile("{\n\t.reg .pred p;\n\t"
                         "mbarrier.try_wait.parity.acquire.cta.shared::cta.b64 p, [%1], 0, 0x989680;\n\t"
                         "selp.b32 %0, 1, 0, p;\n\t}"
                         : "=r"(done) : "r"(mbar_a) : "memory");
        }
    }

    const float4* sd4 = reinterpret_cast<const float4*>(sdata);

    // local min/max: 4 x float4 per thread
    float mn, mx;
    {
        float4 v0 = sd4[tid];
        mn = fminf(fminf(v0.x, v0.y), fminf(v0.z, v0.w));
        mx = fmaxf(fmaxf(v0.x, v0.y), fmaxf(v0.z, v0.w));
        #pragma unroll
        for (int k = 1; k < 4; k++) {
            float4 v = sd4[tid + k * HB];
            mn = fminf(mn, fminf(fminf(v.x, v.y), fminf(v.z, v.w)));
            mx = fmaxf(mx, fmaxf(fmaxf(v.x, v.y), fmaxf(v.z, v.w)));
        }
    }
    #pragma unroll
    for (int o = 16; o > 0; o >>= 1) {
        mn = fminf(mn, __shfl_xor_sync(0xffffffffu, mn, o));
        mx = fmaxf(mx, __shfl_xor_sync(0xffffffffu, mx, o));
    }
    if (lane == 0) { s_red[warp] = mn; s_red[NW + warp] = mx; }
    __syncthreads();
    if (tid == 0) {
        float m = s_red[0], M = s_red[NW];
        #pragma unroll
        for (int i = 1; i < NW; i++) {
            m = fminf(m, s_red[i]);
            M = fmaxf(M, s_red[NW + i]);
        }
        s_mnmx[0] = m;
        s_mnmx[1] = M;
    }

    // publish local (mn,mx); one sync; tid0 reads peer and finalizes
    cluster.sync();
    if (tid == 0) {
        const float* pm = (const float*)cluster.map_shared_rank(s_mnmx, rank ^ 1u);
        float gmn = fminf(s_mnmx[0], pm[0]);
        float gmx = fmaxf(s_mnmx[1], pm[1]);
        s_fin[0] = gmn;
        s_fin[1] = gmx - gmn;
    }
    __syncthreads();

    const float row_mn = s_fin[0];
    const float width  = s_fin[1];
    const float invw   = 128.0f / ((width == 0.0f) ? 1.0f : width);
    const float nmn    = -row_mn * invw;

    // binning: v >= mn guarantees fma >= -1ulp, so int-trunc == floor + low clamp
    unsigned int* h = &hist[warp * BINS];
    #pragma unroll
    for (int k = 0; k < 4; k++) {
        float4 v = sd4[tid + k * HB];
        float vals[4] = {v.x, v.y, v.z, v.w};
        #pragma unroll
        for (int e = 0; e < 4; e++) {
            int b = (int)__fmaf_rn(vals[e], invw, nmn);
            b = min(b, BINS - 1);
            atomicAdd(&h[b], 1u);
        }
    }
    __syncthreads();

    // write this rank's partial counts (as float; exact up to 16384)
    if (tid < BINS) {
        unsigned int c = 0;
        #pragma unroll
        for (int w = 0; w < NW; w++) c += hist[w * BINS + tid];
        g_cnt[((size_t)row * 2 + rank) * BINS + tid] = (float)c;
    }
    if (rank == 1 && tid == 0) {
        g_mnw[row * 2 + 0] = row_mn;
        g_mnw[row * 2 + 1] = width;
    }
}

// ---------------------------------------------------------------------------
// Kernel 2: out = feats @ W^T + b. feats assembled in smem from partial
// counts + (mn,width); WT read from global (L1-resident, coalesced float4).
// ---------------------------------------------------------------------------
__global__ __launch_bounds__(256) void gemm_kernel(const float* __restrict__ bias,
                                                   float* __restrict__ out) {
    __shared__ float sf[GROWS * FPAD];     // 16.6 KB
    const int tid  = threadIdx.x;
    const int row0 = blockIdx.x * GROWS;

    // assemble feats for 16 rows
    for (int n = tid; n < GROWS * FPAD; n += 256) {
        int r   = n / FPAD;
        int i   = n - r * FPAD;
        int row = row0 + r;
        float v;
        if (i < BINS) {
            v = (g_cnt[((size_t)row * 2) * BINS + i] +
                 g_cnt[((size_t)row * 2 + 1) * BINS + i]) * (1.0f / 16384.0f);
        } else if (i < NFEAT) {
            int k   = i - BINS;                      // 0..128
            float t = (float)k * (1.0f / 128.0f);    // exact
            v = g_mnw[row * 2] + t * g_mnw[row * 2 + 1];
        } else {
            v = 0.0f;
        }
        sf[n] = v;
    }
    __syncthreads();

    const int r  = tid >> 4;   // local row 0..15
    const int j4 = tid & 15;   // output float4 group

    const float4* WT4 = reinterpret_cast<const float4*>(g_WT);
    const float*  f   = &sf[r * FPAD];

    float4 acc = make_float4(0.f, 0.f, 0.f, 0.f);
    #pragma unroll 4
    for (int i = 0; i < FPAD; i++) {         // pad entries zero in both operands
        float  fv = f[i];
        float4 wv = WT4[i * (OUT / 4) + j4];
        acc.x += fv * wv.x;
        acc.y += fv * wv.y;
        acc.z += fv * wv.z;
        acc.w += fv * wv.w;
    }
    float4 bb = reinterpret_cast<const float4*>(bias)[j4];
    float4 o  = make_float4(acc.x + bb.x, acc.y + bb.y, acc.z + bb.z, acc.w + bb.w);
    reinterpret_cast<float4*>(out)[(size_t)(row0 + r) * (OUT / 4) + j4] = o;
}

// ---------------------------------------------------------------------------
extern "C" void kernel_launch(void* const* d_in, const int* in_sizes, int n_in,
                              void* d_out, int out_size) {
    const float* x    = (const float*)d_in[0];   // [4096, 16384]
    const float* W    = (const float*)d_in[1];   // [64, 257]
    const float* bias = (const float*)d_in[2];   // [64]
    float* out = (float*)d_out;                  // [4096, 64]

    hist_kernel<<<ROWS * 2, HB, HALF * 4>>>(x, W);
    gemm_kernel<<<ROWS / GROWS, 256>>>(bias, out);
}

// round 6
// speedup vs baseline: 1.3978x; 1.3978x over previous
#include <cuda_runtime.h>
#include <cstdint>

#define ROWS   4096
#define FDIM   16384
#define BINS   128
#define NFEAT  257
#define OUT    64
#define HB     512
#define NW     (HB / 32)      // 16 warps

// Precomputed once per launch (no allocs allowed)
__device__ __align__(16) float g_WTc[BINS * OUT];   // counts-part W, transposed [i][j]
__device__ __align__(16) float g_u[OUT];            // sum_k W[j][128+k]
__device__ __align__(16) float g_v[OUT];            // sum_k (k/128) W[j][128+k]

__device__ __forceinline__ uint32_t smem_u32(const void* p) {
    uint32_t a;
    asm("{ .reg .u64 t; cvta.to.shared.u64 t, %1; cvt.u32.u64 %0, t; }" : "=r"(a) : "l"(p));
    return a;
}

// ---------------------------------------------------------------------------
// Prep: WTc transpose + boundary-part folding (u, v). Tiny.
// ---------------------------------------------------------------------------
__global__ void prep_kernel(const float* __restrict__ W) {
    int idx = blockIdx.x * blockDim.x + threadIdx.x;
    if (idx < BINS * OUT) {
        int i = idx >> 6;       // bin 0..127
        int j = idx & 63;       // output
        g_WTc[idx] = W[j * NFEAT + i];
    }
    if (idx == BINS * OUT + blockDim.x * 0 && false) {}   // (nothing)
    // u, v handled by the last block's first 64 threads
    if (blockIdx.x == gridDim.x - 1 && threadIdx.x < OUT) {
        int j = threadIdx.x;
        const float* wb = W + j * NFEAT + BINS;   // W[j][128..256]
        float u = 0.0f, v = 0.0f;
        #pragma unroll 4
        for (int k = 0; k <= BINS; k++) {         // 129 terms
            float w = wb[k];
            u += w;
            v += (float)k * (1.0f / 128.0f) * w;
        }
        g_u[j] = u;
        g_v[j] = v;
    }
}

// ---------------------------------------------------------------------------
// Fused: TMA row -> smem, min/max, histogram, and epilogue
//   out[row][j] = (sum_b cnt[b] * WTc[b][j]) / 16384 + mn*u[j] + width*v[j] + b[j]
// Dynamic smem: [0,64K) row data | [64K,72K) hist, later aliased to
//   s_cnt[128] (floats) + spart[16][16] float4 partials.
// ---------------------------------------------------------------------------
__global__ __launch_bounds__(HB, 3) void fused_kernel(const float* __restrict__ x,
                                                      const float* __restrict__ bias,
                                                      float* __restrict__ out) {
    extern __shared__ __align__(16) float sdata[];             // 16384 floats
    unsigned int* hist = reinterpret_cast<unsigned int*>(sdata + FDIM);  // 8 KB

    __shared__ float s_red[2 * NW];
    __shared__ float s_mnw[2];
    __shared__ __align__(8) unsigned long long mbar;

    const int row  = blockIdx.x;
    const int tid  = threadIdx.x;
    const int warp = tid >> 5;
    const int lane = tid & 31;

    // zero per-warp histograms
    #pragma unroll
    for (int k = 0; k < (NW * BINS) / HB; k++)
        hist[tid + k * HB] = 0u;

    const uint32_t mbar_a = smem_u32(&mbar);
    const uint32_t data_a = smem_u32(sdata);

    if (tid == 0) {
        asm volatile("mbarrier.init.shared.b64 [%0], 1;" :: "r"(mbar_a) : "memory");
        asm volatile("fence.proxy.async.shared::cta;" ::: "memory");
    }
    __syncthreads();

    if (tid == 0) {
        asm volatile("mbarrier.arrive.expect_tx.shared.b64 _, [%0], %1;"
                     :: "r"(mbar_a), "r"(FDIM * 4) : "memory");
        const float* src = x + (size_t)row * FDIM;
        asm volatile("cp.async.bulk.shared::cta.global.mbarrier::complete_tx::bytes "
                     "[%0], [%1], %2, [%3];"
                     :: "r"(data_a), "l"(src), "r"(FDIM * 4), "r"(mbar_a) : "memory");
    }

    // wait for TMA (parity 0)
    {
        uint32_t done;
        asm volatile("{\n\t.reg .pred p;\n\t"
                     "mbarrier.try_wait.parity.acquire.cta.shared::cta.b64 p, [%1], 0;\n\t"
                     "selp.b32 %0, 1, 0, p;\n\t}"
                     : "=r"(done) : "r"(mbar_a) : "memory");
        while (!done) {
            asm volatile("{\n\t.reg .pred p;\n\t"
                         "mbarrier.try_wait.parity.acquire.cta.shared::cta.b64 p, [%1], 0, 0x989680;\n\t"
                         "selp.b32 %0, 1, 0, p;\n\t}"
                         : "=r"(done) : "r"(mbar_a) : "memory");
        }
    }

    const float4* sd4 = reinterpret_cast<const float4*>(sdata);

    // pass 1: min/max (8 x float4 per thread)
    float mn, mx;
    {
        float4 v0 = sd4[tid];
        mn = fminf(fminf(v0.x, v0.y), fminf(v0.z, v0.w));
        mx = fmaxf(fmaxf(v0.x, v0.y), fmaxf(v0.z, v0.w));
        #pragma unroll
        for (int k = 1; k < 8; k++) {
            float4 v = sd4[tid + k * HB];
            mn = fminf(mn, fminf(fminf(v.x, v.y), fminf(v.z, v.w)));
            mx = fmaxf(mx, fmaxf(fmaxf(v.x, v.y), fmaxf(v.z, v.w)));
        }
    }
    #pragma unroll
    for (int o = 16; o > 0; o >>= 1) {
        mn = fminf(mn, __shfl_xor_sync(0xffffffffu, mn, o));
        mx = fmaxf(mx, __shfl_xor_sync(0xffffffffu, mx, o));
    }
    if (lane == 0) { s_red[warp] = mn; s_red[NW + warp] = mx; }
    __syncthreads();
    if (tid == 0) {
        float m = s_red[0], M = s_red[NW];
        #pragma unroll
        for (int i = 1; i < NW; i++) {
            m = fminf(m, s_red[i]);
            M = fmaxf(M, s_red[NW + i]);
        }
        s_mnw[0] = m;
        s_mnw[1] = M - m;
    }
    __syncthreads();

    const float row_mn = s_mnw[0];
    const float width  = s_mnw[1];
    const float invw   = 128.0f / ((width == 0.0f) ? 1.0f : width);
    const float nmn    = -row_mn * invw;

    // pass 2: binning (v >= mn => fma >= -1ulp, int-trunc == floor + low clamp)
    unsigned int* h = &hist[warp * BINS];
    #pragma unroll
    for (int k = 0; k < 8; k++) {
        float4 v = sd4[tid + k * HB];
        float vals[4] = {v.x, v.y, v.z, v.w};
        #pragma unroll
        for (int e = 0; e < 4; e++) {
            int b = (int)__fmaf_rn(vals[e], invw, nmn);
            b = min(b, BINS - 1);
            atomicAdd(&h[b], 1u);
        }
    }
    __syncthreads();

    // reduce per-warp histograms into registers, then alias hist region
    unsigned int cnt = 0;
    if (tid < BINS) {
        #pragma unroll
        for (int w = 0; w < NW; w++) cnt += hist[w * BINS + tid];
    }
    __syncthreads();                       // hist now dead

    float*  s_cnt = reinterpret_cast<float*>(hist);          // [128]
    float4* spart = reinterpret_cast<float4*>(s_cnt + BINS); // [16][16]

    if (tid < BINS) s_cnt[tid] = (float)cnt;
    __syncthreads();

    // dot: thread = (j4 = tid&15, p = tid>>4); p covers 4 bins
    const int j4 = tid & 15;
    const int p  = tid >> 4;
    const float4* WTc4 = reinterpret_cast<const float4*>(g_WTc);

    float4 acc = make_float4(0.f, 0.f, 0.f, 0.f);
    #pragma unroll
    for (int k = 0; k < 4; k++) {
        int i = p * 4 + k;                 // 0..127
        float  fv = s_cnt[i];
        float4 wv = WTc4[i * (OUT / 4) + j4];
        acc.x += fv * wv.x;
        acc.y += fv * wv.y;
        acc.z += fv * wv.z;
        acc.w += fv * wv.w;
    }
    acc.x += __shfl_xor_sync(0xffffffffu, acc.x, 16);
    acc.y += __shfl_xor_sync(0xffffffffu, acc.y, 16);
    acc.z += __shfl_xor_sync(0xffffffffu, acc.z, 16);
    acc.w += __shfl_xor_sync(0xffffffffu, acc.w, 16);
    if (lane < 16) spart[warp * 16 + lane] = acc;
    __syncthreads();

    if (tid < OUT) {
        const float* sp = reinterpret_cast<const float*>(spart);  // [16][64]
        float s = 0.0f;
        #pragma unroll
        for (int w = 0; w < NW; w++) s += sp[w * OUT + tid];
        float o = s * (1.0f / 16384.0f)
                + row_mn * g_u[tid] + width * g_v[tid] + bias[tid];
        out[(size_t)row * OUT + tid] = o;
    }
}

// ---------------------------------------------------------------------------
extern "C" void kernel_launch(void* const* d_in, const int* in_sizes, int n_in,
                              void* d_out, int out_size) {
    const float* x    = (const float*)d_in[0];   // [4096, 16384]
    const float* W    = (const float*)d_in[1];   // [64, 257]
    const float* bias = (const float*)d_in[2];   // [64]
    float* out = (float*)d_out;                  // [4096, 64]

    const int dyn_smem = (FDIM + 2048) * 4;      // 64 KB row + 8 KB hist/partials
    cudaFuncSetAttribute(fused_kernel, cudaFuncAttributeMaxDynamicSharedMemorySize, dyn_smem);

    prep_kernel<<<(BINS * OUT + 255) / 256, 256>>>(W);
    fused_kernel<<<ROWS, HB, dyn_smem>>>(x, bias, out);
}